// round 1
// baseline (speedup 1.0000x reference)
#include <cuda_runtime.h>

// QuaternionPositionToMatrixLayer: [N,7] f32 (q0,q1,q2,q3,tx,ty,tz) -> [N,3,4] f32 pose.
// Pure bandwidth kernel: smem-staged coalesced float4 input, registers compute,
// float4 output stores (row = 48B = 3x float4, 16B aligned).

constexpr int TPB = 256;                 // rows per block == threads per block
constexpr int IN_F4_PER_BLOCK = TPB * 7 / 4;  // 448 float4s of input per full block

__global__ __launch_bounds__(TPB) void quat_pose_kernel(
    const float4* __restrict__ in4,   // flat view of x, N*7 floats
    float4* __restrict__ out4,        // flat view of out, N*12 floats
    int n_rows)
{
    __shared__ float s[TPB * 7];

    const int t = threadIdx.x;
    const long long row0 = (long long)blockIdx.x * TPB;   // first row of this block
    const int rows_here = min(TPB, n_rows - (int)row0);

    // ---- coalesced staged load: this block's input span as flat float4s ----
    // Block input span: rows_here*7 floats. For full blocks: 448 float4s, 16B aligned
    // (row0*7*4 bytes, row0 % 4 == 0 since TPB divisible by 4).
    {
        const long long base4 = row0 * 7 / 4;             // exact: row0 multiple of 4
        const int nf4 = rows_here * 7 / 4;                // full blocks: 448
        const int tail_floats = rows_here * 7 - nf4 * 4;  // 0 for full blocks
        float4* s4 = reinterpret_cast<float4*>(s);
        #pragma unroll
        for (int i = 0; i < 2; ++i) {
            int idx = t + i * TPB;
            if (idx < nf4) s4[idx] = in4[base4 + idx];
        }
        if (tail_floats) {
            // generic tail path (not hit for N=4,000,000)
            const float* inf = reinterpret_cast<const float*>(in4);
            for (int k = t; k < tail_floats; k += TPB)
                s[nf4 * 4 + k] = inf[row0 * 7 + nf4 * 4 + k];
        }
    }
    __syncthreads();

    if (t >= rows_here) return;

    // ---- per-row compute from smem (stride-7 word access: bank-conflict free) ----
    const float* r = s + t * 7;
    const float q0 = r[0], q1 = r[1], q2 = r[2], q3 = r[3];
    const float tx = r[4], ty = r[5], tz = r[6];

    const float q0q0 = q0 * q0, q1q1 = q1 * q1, q2q2 = q2 * q2, q3q3 = q3 * q3;
    const float q0q1 = q0 * q1, q0q2 = q0 * q2, q0q3 = q0 * q3;
    const float q1q2 = q1 * q2, q1q3 = q1 * q3, q2q3 = q2 * q3;

    float4 o0, o1, o2;
    o0.x = q0q0 + q1q1 - q2q2 - q3q3;     // r00
    o0.y = 2.0f * (q1q2 - q0q3);          // r01
    o0.z = 2.0f * (q1q3 + q0q2);          // r02
    o0.w = tx;
    o1.x = 2.0f * (q1q2 + q0q3);          // r10
    o1.y = q0q0 - q1q1 + q2q2 - q3q3;     // r11
    o1.z = 2.0f * (q2q3 - q0q1);          // r12
    o1.w = ty;
    o2.x = 2.0f * (q1q3 - q0q2);          // r20
    o2.y = 2.0f * (q2q3 + q0q1);          // r21
    o2.z = q0q0 - q1q1 - q2q2 + q3q3;     // r22
    o2.w = tz;

    // ---- output: 3 aligned float4 stores per row ----
    const long long ob = (row0 + t) * 3;  // float4 index (48B per row)
    out4[ob + 0] = o0;
    out4[ob + 1] = o1;
    out4[ob + 2] = o2;
}

extern "C" void kernel_launch(void* const* d_in, const int* in_sizes, int n_in,
                              void* d_out, int out_size)
{
    const float4* in4 = (const float4*)d_in[0];
    float4* out4 = (float4*)d_out;
    const int n_rows = in_sizes[0] / 7;
    const int grid = (n_rows + TPB - 1) / TPB;   // 15625 for N=4M
    quat_pose_kernel<<<grid, TPB>>>(in4, out4, n_rows);
}

// round 2
// speedup vs baseline: 1.7926x; 1.7926x over previous
#include <cuda_runtime.h>

// QuaternionPositionToMatrixLayer: [N,7] f32 (q0,q1,q2,q3,tx,ty,tz) -> [N,3,4] f32 pose.
// Pure bandwidth kernel. Both input AND output are staged through shared memory so
// every global transaction is a flat, fully-coalesced float4 (4 wavefronts/warp-op).
// Streaming cache hints (.cs) keep the write stream from thrashing L2.

constexpr int TPB = 256;   // rows per block == threads per block

__global__ __launch_bounds__(TPB) void quat_pose_kernel(
    const float4* __restrict__ in4,   // flat view of x, N*7 floats
    float4* __restrict__ out4,        // flat view of out, N*12 floats
    int n_rows)
{
    __shared__ float  s_in[TPB * 7];          // 7168 B
    __shared__ float4 s_out[TPB * 3];         // 12288 B

    const int t = threadIdx.x;
    const long long row0 = (long long)blockIdx.x * TPB;
    const int rows_here = min(TPB, n_rows - (int)row0);

    // ---- coalesced staged input: block's span as flat float4s ----
    {
        const long long base4 = row0 * 7 / 4;             // exact: row0 % 4 == 0
        const int nf4 = rows_here * 7 / 4;                // 448 for full blocks
        const int tail_floats = rows_here * 7 - nf4 * 4;  // 0 for full blocks
        float4* s4 = reinterpret_cast<float4*>(s_in);
        #pragma unroll
        for (int i = 0; i < 2; ++i) {
            int idx = t + i * TPB;
            if (idx < nf4) s4[idx] = __ldcs(&in4[base4 + idx]);
        }
        if (tail_floats) {   // generic tail path (not hit for N=4,000,000)
            const float* inf = reinterpret_cast<const float*>(in4);
            for (int k = t; k < tail_floats; k += TPB)
                s_in[nf4 * 4 + k] = inf[row0 * 7 + nf4 * 4 + k];
        }
    }
    __syncthreads();

    // ---- per-row compute (stride-7 smem reads: bank-conflict free) ----
    if (t < rows_here) {
        const float* r = s_in + t * 7;
        const float q0 = r[0], q1 = r[1], q2 = r[2], q3 = r[3];
        const float tx = r[4], ty = r[5], tz = r[6];

        const float q0q0 = q0 * q0, q1q1 = q1 * q1, q2q2 = q2 * q2, q3q3 = q3 * q3;
        const float q0q1 = q0 * q1, q0q2 = q0 * q2, q0q3 = q0 * q3;
        const float q1q2 = q1 * q2, q1q3 = q1 * q3, q2q3 = q2 * q3;

        float4 o0, o1, o2;
        o0.x = q0q0 + q1q1 - q2q2 - q3q3;     // r00
        o0.y = 2.0f * (q1q2 - q0q3);          // r01
        o0.z = 2.0f * (q1q3 + q0q2);          // r02
        o0.w = tx;
        o1.x = 2.0f * (q1q2 + q0q3);          // r10
        o1.y = q0q0 - q1q1 + q2q2 - q3q3;     // r11
        o1.z = 2.0f * (q2q3 - q0q1);          // r12
        o1.w = ty;
        o2.x = 2.0f * (q1q3 - q0q2);          // r20
        o2.y = 2.0f * (q2q3 + q0q1);          // r21
        o2.z = q0q0 - q1q1 - q2q2 + q3q3;     // r22
        o2.w = tz;

        // STS.128 at float4-stride 3 (word stride 12): per 8-lane phase banks are
        // {0,12,24,4,16,28,8,20} — all distinct, conflict-free.
        s_out[t * 3 + 0] = o0;
        s_out[t * 3 + 1] = o1;
        s_out[t * 3 + 2] = o2;
    }
    __syncthreads();

    // ---- flat coalesced output: 768 float4s per full block ----
    {
        const long long obase4 = row0 * 3;     // float4 index of block's output span
        const int nf4 = rows_here * 3;         // 768 for full blocks
        #pragma unroll
        for (int i = 0; i < 3; ++i) {
            int idx = t + i * TPB;
            if (idx < nf4) __stcs(&out4[obase4 + idx], s_out[idx]);
        }
    }
}

extern "C" void kernel_launch(void* const* d_in, const int* in_sizes, int n_in,
                              void* d_out, int out_size)
{
    const float4* in4 = (const float4*)d_in[0];
    float4* out4 = (float4*)d_out;
    const int n_rows = in_sizes[0] / 7;
    const int grid = (n_rows + TPB - 1) / TPB;   // 15625 for N=4M
    quat_pose_kernel<<<grid, TPB>>>(in4, out4, n_rows);
}

// round 7
// speedup vs baseline: 1.8369x; 1.0247x over previous
#include <cuda_runtime.h>
#include <cstdint>

// QuaternionPositionToMatrixLayer: [N,7] f32 -> [N,3,4] f32 pose. Bandwidth-bound.
// Input: smem-staged coalesced float4 LDG. Output: staged to smem, then drained by a
// single 1D cp.async.bulk (TMA) store of the block's contiguous 12288B span —
// removes all output LDS+STG wavefronts from the LSU/L1 path.

constexpr int TPB = 256;   // rows per block == threads per block

__global__ __launch_bounds__(TPB) void quat_pose_kernel(
    const float4* __restrict__ in4,   // flat view of x, N*7 floats
    float4* __restrict__ out4,        // flat view of out, N*12 floats
    int n_rows)
{
    __shared__ float  s_in[TPB * 7];                       // 7168 B
    __shared__ __align__(16) float4 s_out[TPB * 3];        // 12288 B

    const int t = threadIdx.x;
    const long long row0 = (long long)blockIdx.x * TPB;
    const int rows_here = min(TPB, n_rows - (int)row0);

    // ---- coalesced staged input ----
    {
        const long long base4 = row0 * 7 / 4;             // exact: row0 % 4 == 0
        const int nf4 = rows_here * 7 / 4;                // 448 for full blocks
        const int tail_floats = rows_here * 7 - nf4 * 4;  // 0 for full blocks
        float4* s4 = reinterpret_cast<float4*>(s_in);
        #pragma unroll
        for (int i = 0; i < 2; ++i) {
            int idx = t + i * TPB;
            if (idx < nf4) s4[idx] = __ldcs(&in4[base4 + idx]);
        }
        if (tail_floats) {   // generic tail path (not hit for N=4,000,000)
            const float* inf = reinterpret_cast<const float*>(in4);
            for (int k = t; k < tail_floats; k += TPB)
                s_in[nf4 * 4 + k] = inf[row0 * 7 + nf4 * 4 + k];
        }
    }
    __syncthreads();

    // ---- per-row compute (stride-7 smem reads: bank-conflict free) ----
    if (t < rows_here) {
        const float* r = s_in + t * 7;
        const float q0 = r[0], q1 = r[1], q2 = r[2], q3 = r[3];
        const float tx = r[4], ty = r[5], tz = r[6];

        const float q0q0 = q0 * q0, q1q1 = q1 * q1, q2q2 = q2 * q2, q3q3 = q3 * q3;
        const float q0q1 = q0 * q1, q0q2 = q0 * q2, q0q3 = q0 * q3;
        const float q1q2 = q1 * q2, q1q3 = q1 * q3, q2q3 = q2 * q3;

        float4 o0, o1, o2;
        o0.x = q0q0 + q1q1 - q2q2 - q3q3;     // r00
        o0.y = 2.0f * (q1q2 - q0q3);          // r01
        o0.z = 2.0f * (q1q3 + q0q2);          // r02
        o0.w = tx;
        o1.x = 2.0f * (q1q2 + q0q3);          // r10
        o1.y = q0q0 - q1q1 + q2q2 - q3q3;     // r11
        o1.z = 2.0f * (q2q3 - q0q1);          // r12
        o1.w = ty;
        o2.x = 2.0f * (q1q3 - q0q2);          // r20
        o2.y = 2.0f * (q2q3 + q0q1);          // r21
        o2.z = q0q0 - q1q1 - q2q2 + q3q3;     // r22
        o2.w = tz;

        // STS.128, float4-stride 3 (word stride 12): conflict-free per 8-lane phase.
        s_out[t * 3 + 0] = o0;
        s_out[t * 3 + 1] = o1;
        s_out[t * 3 + 2] = o2;
    }
    __syncthreads();

    // ---- output drain: single 1D TMA bulk store of the contiguous span ----
    if (t == 0 && rows_here > 0) {
        // Make generic-proxy STS visible to the async (TMA) proxy.
        asm volatile("fence.proxy.async.shared::cta;" ::: "memory");

        unsigned int s_addr;
        asm("{ .reg .u64 a; cvta.to.shared.u64 a, %1; cvt.u32.u64 %0, a; }"
            : "=r"(s_addr) : "l"(s_out));
        void* gptr = (void*)(out4 + row0 * 3);
        const unsigned int bytes = (unsigned int)(rows_here * 48);   // multiple of 16

        asm volatile(
            "cp.async.bulk.global.shared::cta.bulk_group [%0], [%1], %2;"
            :: "l"(gptr), "r"(s_addr), "r"(bytes) : "memory");
        asm volatile("cp.async.bulk.commit_group;" ::: "memory");
        // Smem must stay live until the TMA engine has read it.
        asm volatile("cp.async.bulk.wait_group.read 0;" ::: "memory");
    }
}

extern "C" void kernel_launch(void* const* d_in, const int* in_sizes, int n_in,
                              void* d_out, int out_size)
{
    const float4* in4 = (const float4*)d_in[0];
    float4* out4 = (float4*)d_out;
    const int n_rows = in_sizes[0] / 7;
    const int grid = (n_rows + TPB - 1) / TPB;   // 15625 for N=4M
    quat_pose_kernel<<<grid, TPB>>>(in4, out4, n_rows);
}